// round 8
// baseline (speedup 1.0000x reference)
#include <cuda_runtime.h>
#include <cuda_fp16.h>
#include <cstdint>
#include <math.h>

#define LQ   40000
#define DMOD 256
#define NH   8
#define NP   4
#define DH   32
#define HSP  200
#define WSP  200
#define GQ   8

// ---------------- scratch (no allocations allowed) ----------------
__device__ __half g_value[LQ * DMOD];    // value projection in fp16
__device__ float g_oa[LQ * 96];
__device__ float g_sampled[LQ * DMOD];   // tf32-pre-rounded
__device__ float g_inp[LQ * DMOD];       // tf32-rounded input_flatten
__device__ float g_wv[DMOD * DMOD];
__device__ float g_wout[DMOD * DMOD];

// ---------------- helpers ----------------
__device__ __forceinline__ uint32_t tf32_rna(float x) {
    uint32_t u;
    asm("cvt.rna.tf32.f32 %0, %1;" : "=r"(u) : "f"(x));
    return u;
}
__device__ __forceinline__ void mma16n8k8(float* c, const uint32_t* a, const uint32_t* b) {
    asm volatile(
        "mma.sync.aligned.m16n8k8.row.col.f32.tf32.tf32.f32 "
        "{%0,%1,%2,%3}, {%4,%5,%6,%7}, {%8,%9}, {%0,%1,%2,%3};"
        : "+f"(c[0]), "+f"(c[1]), "+f"(c[2]), "+f"(c[3])
        : "r"(a[0]), "r"(a[1]), "r"(a[2]), "r"(a[3]), "r"(b[0]), "r"(b[1]));
}
__device__ __forceinline__ void ldsm4(uint32_t& r0, uint32_t& r1, uint32_t& r2,
                                      uint32_t& r3, uint32_t addr) {
    asm volatile("ldmatrix.sync.aligned.m8n8.x4.shared.b16 {%0,%1,%2,%3}, [%4];"
                 : "=r"(r0), "=r"(r1), "=r"(r2), "=r"(r3) : "r"(addr));
}
__device__ __forceinline__ void cp_async16(uint32_t dst, const void* src, uint32_t sz) {
    asm volatile("cp.async.cg.shared.global [%0], [%1], 16, %2;"
                 :: "r"(dst), "l"(src), "r"(sz));
}
__device__ __forceinline__ void cp_commit() {
    asm volatile("cp.async.commit_group;" ::: "memory");
}
__device__ __forceinline__ void cp_wait1() {
    asm volatile("cp.async.wait_group 1;" ::: "memory");
}

template<typename T> __device__ __forceinline__ void store2(T* p, float x, float y);
template<> __device__ __forceinline__ void store2<float>(float* p, float x, float y) {
    *reinterpret_cast<float2*>(p) = make_float2(x, y);
}
template<> __device__ __forceinline__ void store2<__half>(__half* p, float x, float y) {
    *reinterpret_cast<__half2*>(p) = __floats2half2_rn(x, y);
}

// ---------------- tf32 rounding pass ----------------
__global__ void round_tf32(const float4* __restrict__ src, uint4* __restrict__ dst, int n4) {
    int i = blockIdx.x * blockDim.x + threadIdx.x;
    if (i < n4) {
        float4 v = src[i];
        dst[i] = make_uint4(tf32_rna(v.x), tf32_rna(v.y), tf32_rna(v.z), tf32_rna(v.w));
    }
}

// ============ pipelined tf32 GEMM: C[M,N] = A[M,256] @ B[N,256]^T + bias ============
// CTA tile 128x128, 8 warps (4 row x 2 col), warp tile 32x64.
// 3-stage cp.async; ldmatrix fragments; inputs pre-rounded tf32.
template<typename OutT>
__global__ __launch_bounds__(256, 2)
void pipe_gemm(const float* __restrict__ A, const float* __restrict__ Bw,
               const float* __restrict__ bias, OutT* __restrict__ C, int M, int N) {
    constexpr int BM = 128;
    constexpr int BN = 128;
    constexpr int BK = 32;
    constexpr int LD = 36;
    constexpr int NCHUNK = DMOD / BK;   // 8
    constexpr int ASZ = BM * LD;
    constexpr int BSZ = BN * LD;
    constexpr int SSZ = ASZ + BSZ;

    extern __shared__ float sm[];
    const uint32_t smem_u32 = (uint32_t)__cvta_generic_to_shared(sm);

    const int tid = threadIdx.x;
    const int wid = tid >> 5;
    const int lane = tid & 31;
    const int wm = wid & 3;             // 32-row group
    const int wn = wid >> 2;            // 64-col group (0..1)
    const int bm = blockIdx.y * BM;
    const int bn = blockIdx.x * BN;
    const int lq = lane >> 2;
    const int lr = lane & 3;

    // ldmatrix lane offsets
    const int arow_l = wm * 32 + (lane & 15);
    const int acol_l = (lane >> 4) << 2;
    const int brow_l = wn * 64 + (lane & 7) + ((lane >> 4) << 3);
    const int bcol_l = ((lane >> 3) & 1) << 2;

    // copy coords: row = tid>>3 + 32*i, col word = (tid&7)*4
    const int r0 = tid >> 3;
    const int f4 = (tid & 7) * 4;
    const float* abase = A + (size_t)(bm + r0) * DMOD + f4;   // guarded by sz
    const float* bbase = Bw + (size_t)(bn + r0) * DMOD + f4;
    uint32_t asz[4];
#pragma unroll
    for (int i = 0; i < 4; i++) asz[i] = (bm + r0 + 32 * i) < M ? 16u : 0u;

    auto issue_stage = [&](int buf, int k0) {
        const uint32_t sb = smem_u32 + (uint32_t)(buf * SSZ) * 4u;
#pragma unroll
        for (int i = 0; i < 4; i++)
            cp_async16(sb + (uint32_t)((r0 + 32 * i) * LD + f4) * 4u,
                       abase + k0 + (size_t)(32 * i) * DMOD, asz[i]);
#pragma unroll
        for (int i = 0; i < 4; i++)
            cp_async16(sb + (uint32_t)(ASZ + (r0 + 32 * i) * LD + f4) * 4u,
                       bbase + k0 + (size_t)(32 * i) * DMOD, 16u);
    };

    float acc[2][8][4];
#pragma unroll
    for (int i = 0; i < 2; i++)
#pragma unroll
        for (int j = 0; j < 8; j++)
#pragma unroll
            for (int r = 0; r < 4; r++) acc[i][j][r] = 0.0f;

    issue_stage(0, 0); cp_commit();
    issue_stage(1, BK); cp_commit();

    for (int c = 0; c < NCHUNK; c++) {
        cp_wait1();
        __syncthreads();
        if (c + 2 < NCHUNK) issue_stage((c + 2) % 3, (c + 2) * BK);
        cp_commit();

        const uint32_t As_u = smem_u32 + (uint32_t)((c % 3) * SSZ) * 4u;
        const uint32_t Bs_u = As_u + (uint32_t)ASZ * 4u;
#pragma unroll
        for (int ks = 0; ks < 4; ks++) {
            const int kk = ks * 8;
            uint32_t a[2][4], b[4][4];
#pragma unroll
            for (int mi = 0; mi < 2; mi++)
                ldsm4(a[mi][0], a[mi][1], a[mi][2], a[mi][3],
                      As_u + (uint32_t)((arow_l + mi * 16) * LD + kk + acol_l) * 4u);
#pragma unroll
            for (int nb = 0; nb < 4; nb++)
                ldsm4(b[nb][0], b[nb][1], b[nb][2], b[nb][3],
                      Bs_u + (uint32_t)((brow_l + nb * 16) * LD + kk + bcol_l) * 4u);
#pragma unroll
            for (int mi = 0; mi < 2; mi++)
#pragma unroll
                for (int nb = 0; nb < 4; nb++) {
                    mma16n8k8(acc[mi][nb * 2 + 0], a[mi], &b[nb][0]);
                    mma16n8k8(acc[mi][nb * 2 + 1], a[mi], &b[nb][2]);
                }
        }
    }

    // epilogue
#pragma unroll
    for (int mi = 0; mi < 2; mi++) {
        const int row0 = bm + wm * 32 + mi * 16 + lq;
#pragma unroll
        for (int ni = 0; ni < 8; ni++) {
            const int col = bn + wn * 64 + ni * 8 + lr * 2;
            const float bz0 = bias[col], bz1 = bias[col + 1];
            if (row0 < M)
                store2(C + (size_t)row0 * N + col,
                       acc[mi][ni][0] + bz0, acc[mi][ni][1] + bz1);
            if (row0 + 8 < M)
                store2(C + (size_t)(row0 + 8) * N + col,
                       acc[mi][ni][2] + bz0, acc[mi][ni][3] + bz1);
        }
    }
}

// ============ [off|attn] projection: (query+qpos) @ [W_off; W_attn]^T + bias ============
__global__ __launch_bounds__(384, 1)
void oa_gemm(const float* __restrict__ A, const float* __restrict__ A2,
             const float* __restrict__ B1, const float* __restrict__ B2,
             const float* __restrict__ bias1, const float* __restrict__ bias2,
             float* __restrict__ C, int M) {
    constexpr int BM = 128, BN = 96, BK = 32, LD = 36;
    constexpr int NT = 384;
    constexpr int AITER = 3;
    constexpr int BITER = 2;

    __shared__ float As[BM * LD];
    __shared__ float Bs[BN * LD];

    const int tid = threadIdx.x;
    const int wid = tid >> 5;
    const int lane = tid & 31;
    const int wm = wid & 3;
    const int wn = wid >> 2;
    const int bm = blockIdx.y * BM;
    const int lq = lane >> 2;
    const int lr = lane & 3;

    const int arow_l = wm * 32 + (lane & 15);
    const int acol_l = (lane >> 4) << 2;
    const int brow_l = wn * 32 + (lane & 7) + ((lane >> 4) << 3);
    const int bcol_l = ((lane >> 3) & 1) << 2;
    const uint32_t As_u = (uint32_t)__cvta_generic_to_shared(As);
    const uint32_t Bs_u = (uint32_t)__cvta_generic_to_shared(Bs);

    float acc[2][4][4];
#pragma unroll
    for (int i = 0; i < 2; i++)
#pragma unroll
        for (int j = 0; j < 4; j++)
#pragma unroll
            for (int r = 0; r < 4; r++) acc[i][j][r] = 0.0f;

    float4 ra[AITER], rb[BITER];
    auto load_tiles = [&](int k0) {
#pragma unroll
        for (int i = 0; i < AITER; i++) {
            int idx = tid + i * NT;
            if (idx < BM * 8) {
                int row = idx >> 3, f = idx & 7;
                int gr = bm + row; gr = gr < M ? gr : M - 1;
                float4 v = *reinterpret_cast<const float4*>(A + (size_t)gr * DMOD + k0 + f * 4);
                float4 w = *reinterpret_cast<const float4*>(A2 + (size_t)gr * DMOD + k0 + f * 4);
                v.x += w.x; v.y += w.y; v.z += w.z; v.w += w.w;
                ra[i] = v;
            }
        }
#pragma unroll
        for (int i = 0; i < BITER; i++) {
            int idx = tid + i * NT;
            int row = idx >> 3, f = idx & 7;
            const float* bp = row < 64 ? B1 + (size_t)row * DMOD
                                       : B2 + (size_t)(row - 64) * DMOD;
            rb[i] = *reinterpret_cast<const float4*>(bp + k0 + f * 4);
        }
    };
    auto store_smem = [&]() {
#pragma unroll
        for (int i = 0; i < AITER; i++) {
            int idx = tid + i * NT;
            if (idx < BM * 8) {
                int row = idx >> 3, f = idx & 7;
                uint4 t = make_uint4(tf32_rna(ra[i].x), tf32_rna(ra[i].y),
                                     tf32_rna(ra[i].z), tf32_rna(ra[i].w));
                *reinterpret_cast<uint4*>(&As[row * LD + f * 4]) = t;
            }
        }
#pragma unroll
        for (int i = 0; i < BITER; i++) {
            int idx = tid + i * NT;
            int row = idx >> 3, f = idx & 7;
            uint4 t = make_uint4(tf32_rna(rb[i].x), tf32_rna(rb[i].y),
                                 tf32_rna(rb[i].z), tf32_rna(rb[i].w));
            *reinterpret_cast<uint4*>(&Bs[row * LD + f * 4]) = t;
        }
    };

    load_tiles(0);
    for (int c = 0; c < DMOD / BK; c++) {
        store_smem();
        __syncthreads();
        if (c < DMOD / BK - 1) load_tiles((c + 1) * BK);
#pragma unroll
        for (int ks = 0; ks < 4; ks++) {
            const int kk = ks * 8;
            uint32_t a[2][4], bA[4], bB[4];
#pragma unroll
            for (int mi = 0; mi < 2; mi++)
                ldsm4(a[mi][0], a[mi][1], a[mi][2], a[mi][3],
                      As_u + (uint32_t)((arow_l + mi * 16) * LD + kk + acol_l) * 4u);
            ldsm4(bA[0], bA[1], bA[2], bA[3],
                  Bs_u + (uint32_t)(brow_l * LD + kk + bcol_l) * 4u);
            ldsm4(bB[0], bB[1], bB[2], bB[3],
                  Bs_u + (uint32_t)((brow_l + 16) * LD + kk + bcol_l) * 4u);
#pragma unroll
            for (int mi = 0; mi < 2; mi++) {
                mma16n8k8(acc[mi][0], a[mi], &bA[0]);
                mma16n8k8(acc[mi][1], a[mi], &bA[2]);
                mma16n8k8(acc[mi][2], a[mi], &bB[0]);
                mma16n8k8(acc[mi][3], a[mi], &bB[2]);
            }
        }
        __syncthreads();
    }

#pragma unroll
    for (int mi = 0; mi < 2; mi++) {
        const int row0 = bm + wm * 32 + mi * 16 + lq;
#pragma unroll
        for (int ni = 0; ni < 4; ni++) {
            const int col = wn * 32 + ni * 8 + lr * 2;
            const float bz0 = col < 64 ? bias1[col] : bias2[col - 64];
            const float bz1 = (col + 1) < 64 ? bias1[col + 1] : bias2[col + 1 - 64];
            if (row0 < M) {
                float2 o = make_float2(acc[mi][ni][0] + bz0, acc[mi][ni][1] + bz1);
                *reinterpret_cast<float2*>(C + (size_t)row0 * 96 + col) = o;
            }
            if (row0 + 8 < M) {
                float2 o = make_float2(acc[mi][ni][2] + bz0, acc[mi][ni][3] + bz1);
                *reinterpret_cast<float2*>(C + (size_t)(row0 + 8) * 96 + col) = o;
            }
        }
    }
}

// ---------------- sampler: scalar phase + fp16 gather phase ----------------
__global__ __launch_bounds__(256)
void sample_kernel(const float* __restrict__ refpts) {
    __shared__ int2 s_pc[256 * 4];

    const int tid = threadIdx.x;
    const int q0 = blockIdx.x * GQ;
    const int qi = tid >> 5;
    const int h = (tid >> 2) & 7;
    const int p = tid & 3;
    const int q = q0 + qi;

    const float refx = refpts[q * 2 + 0];
    const float refy = refpts[q * 2 + 1];
    const float* row = g_oa + (size_t)q * 96;
    const float lg = row[64 + h * 4 + p];
    const float ox = row[h * 8 + p * 2 + 0];
    const float oy = row[h * 8 + p * 2 + 1];

    float mx = lg;
    mx = fmaxf(mx, __shfl_xor_sync(0xFFFFFFFFu, mx, 1));
    mx = fmaxf(mx, __shfl_xor_sync(0xFFFFFFFFu, mx, 2));
    float e = expf(lg - mx);
    float s = e;
    s += __shfl_xor_sync(0xFFFFFFFFu, s, 1);
    s += __shfl_xor_sync(0xFFFFFFFFu, s, 2);
    const float ap = e / s;

    const float x = (refx + ox * (1.0f / WSP)) * WSP - 0.5f;
    const float y = (refy + oy * (1.0f / HSP)) * HSP - 0.5f;
    const float x0f = floorf(x), y0f = floorf(y);
    const int x0 = (int)x0f, y0 = (int)y0f;
    const float lw = x - x0f, lh = y - y0f;
    const int x1 = x0 + 1, y1 = y0 + 1;

    const float wc[4] = { (1.0f - lh) * (1.0f - lw), (1.0f - lh) * lw,
                          lh * (1.0f - lw),          lh * lw };
    const int xs[4] = { x0, x1, x0, x1 };
    const int ys[4] = { y0, y0, y1, y1 };
#pragma unroll
    for (int c = 0; c < 4; c++) {
        const bool v = (xs[c] >= 0) & (xs[c] < WSP) & (ys[c] >= 0) & (ys[c] < HSP);
        const float w = v ? ap * wc[c] : 0.0f;
        const int idx = v ? (ys[c] * WSP + xs[c]) : 0;
        s_pc[tid * 4 + c] = make_int2(idx, __float_as_int(w));
    }
    __syncthreads();

    const int wid = tid >> 5, lane = tid & 31;
    float* outp = g_sampled + (size_t)(q0 + wid) * DMOD + lane;
#pragma unroll
    for (int hh = 0; hh < NH; hh++) {
        const __half* vb = g_value + hh * DH + lane;
        const int base = (wid * 32 + hh * 4) * 4;
        float acc0 = 0.0f, acc1 = 0.0f;
#pragma unroll
        for (int pc = 0; pc < 16; pc += 2) {
            int2 a = s_pc[base + pc];
            int2 b = s_pc[base + pc + 1];
            acc0 += __int_as_float(a.y) * __half2float(vb[(size_t)a.x * DMOD]);
            acc1 += __int_as_float(b.y) * __half2float(vb[(size_t)b.x * DMOD]);
        }
        outp[hh * DH] = __uint_as_float(tf32_rna(acc0 + acc1));
    }
}

// ---------------- launch ----------------
extern "C" void kernel_launch(void* const* d_in, const int* in_sizes, int n_in,
                              void* d_out, int out_size) {
    const float* query  = (const float*)d_in[0];
    const float* qpos   = (const float*)d_in[1];
    const float* refpts = (const float*)d_in[2];
    const float* inp    = (const float*)d_in[3];
    const float* Wv     = (const float*)d_in[4];
    const float* bv     = (const float*)d_in[5];
    const float* Woff   = (const float*)d_in[6];
    const float* boff   = (const float*)d_in[7];
    const float* Wattn  = (const float*)d_in[8];
    const float* battn  = (const float*)d_in[9];
    const float* Wout   = (const float*)d_in[10];
    const float* bout   = (const float*)d_in[11];
    float* out = (float*)d_out;

    __half* p_val;
    float *p_oa, *p_samp, *p_inp, *p_wv, *p_wout;
    cudaGetSymbolAddress((void**)&p_val, g_value);
    cudaGetSymbolAddress((void**)&p_oa, g_oa);
    cudaGetSymbolAddress((void**)&p_samp, g_sampled);
    cudaGetSymbolAddress((void**)&p_inp, g_inp);
    cudaGetSymbolAddress((void**)&p_wv, g_wv);
    cudaGetSymbolAddress((void**)&p_wout, g_wout);

    const int gy = (LQ + 127) / 128;  // 313
    const int SMEM_PIPE = 3 * (128 * 36 + 128 * 36) * 4;  // 110592
    cudaFuncSetAttribute(pipe_gemm<__half>, cudaFuncAttributeMaxDynamicSharedMemorySize, SMEM_PIPE);
    cudaFuncSetAttribute(pipe_gemm<float>,  cudaFuncAttributeMaxDynamicSharedMemorySize, SMEM_PIPE);

    // 0. tf32-round GEMM operands once
    {
        int n4 = LQ * DMOD / 4;
        round_tf32<<<(n4 + 255) / 256, 256>>>((const float4*)inp, (uint4*)p_inp, n4);
        int w4 = DMOD * DMOD / 4;
        round_tf32<<<(w4 + 255) / 256, 256>>>((const float4*)Wv, (uint4*)p_wv, w4);
        round_tf32<<<(w4 + 255) / 256, 256>>>((const float4*)Wout, (uint4*)p_wout, w4);
    }

    // 1. value = input_flatten @ W_value^T + b_value  (fp16 output)
    pipe_gemm<__half><<<dim3(2, gy), 256, SMEM_PIPE>>>(p_inp, p_wv, bv, p_val, LQ, DMOD);

    // 2. [off | attn] = (query+query_pos) @ [W_off; W_attn]^T + bias
    oa_gemm<<<dim3(1, gy), 384>>>(query, qpos, Woff, Wattn, boff, battn, p_oa, LQ);

    // 3. fused softmax + bilinear sampling (fp16 gathers)
    sample_kernel<<<LQ / GQ, 256>>>(refpts);

    // 4. out = sampled @ W_out^T + b_out
    pipe_gemm<float><<<dim3(2, gy), 256, SMEM_PIPE>>>(p_samp, p_wout, bout, out, LQ, DMOD);
}

// round 10
// speedup vs baseline: 1.2308x; 1.2308x over previous
#include <cuda_runtime.h>
#include <cuda_fp16.h>
#include <cstdint>
#include <math.h>

#define LQ   40000
#define DMOD 256
#define NH   8
#define NP   4
#define DH   32
#define HSP  200
#define WSP  200
#define GQ   8

// ---------------- scratch (no allocations allowed) ----------------
__device__ __half g_value[LQ * DMOD];     // value projection (fp16)
__device__ float  g_oa[LQ * 96];
__device__ __half g_sampled[LQ * DMOD];   // sampled output (fp16)
__device__ __half g_inp[LQ * DMOD];       // fp16 input_flatten
__device__ __half g_wv[DMOD * DMOD];      // fp16 W_value
__device__ __half g_wout[DMOD * DMOD];    // fp16 W_out

// ---------------- helpers ----------------
__device__ __forceinline__ uint32_t tf32_rna(float x) {
    uint32_t u;
    asm("cvt.rna.tf32.f32 %0, %1;" : "=r"(u) : "f"(x));
    return u;
}
__device__ __forceinline__ uint32_t h2_to_u32(__half2 h) {
    uint32_t u;
    memcpy(&u, &h, 4);
    return u;
}
__device__ __forceinline__ void mma16n8k8(float* c, const uint32_t* a, const uint32_t* b) {
    asm volatile(
        "mma.sync.aligned.m16n8k8.row.col.f32.tf32.tf32.f32 "
        "{%0,%1,%2,%3}, {%4,%5,%6,%7}, {%8,%9}, {%0,%1,%2,%3};"
        : "+f"(c[0]), "+f"(c[1]), "+f"(c[2]), "+f"(c[3])
        : "r"(a[0]), "r"(a[1]), "r"(a[2]), "r"(a[3]), "r"(b[0]), "r"(b[1]));
}
__device__ __forceinline__ void mma16n8k16h(float* c, const uint32_t* a, const uint32_t* b) {
    asm volatile(
        "mma.sync.aligned.m16n8k16.row.col.f32.f16.f16.f32 "
        "{%0,%1,%2,%3}, {%4,%5,%6,%7}, {%8,%9}, {%0,%1,%2,%3};"
        : "+f"(c[0]), "+f"(c[1]), "+f"(c[2]), "+f"(c[3])
        : "r"(a[0]), "r"(a[1]), "r"(a[2]), "r"(a[3]), "r"(b[0]), "r"(b[1]));
}
__device__ __forceinline__ void ldsm4(uint32_t& r0, uint32_t& r1, uint32_t& r2,
                                      uint32_t& r3, uint32_t addr) {
    asm volatile("ldmatrix.sync.aligned.m8n8.x4.shared.b16 {%0,%1,%2,%3}, [%4];"
                 : "=r"(r0), "=r"(r1), "=r"(r2), "=r"(r3) : "r"(addr));
}
__device__ __forceinline__ void cp_async16(uint32_t dst, const void* src, uint32_t sz) {
    asm volatile("cp.async.cg.shared.global [%0], [%1], 16, %2;"
                 :: "r"(dst), "l"(src), "r"(sz));
}
__device__ __forceinline__ void cp_commit() {
    asm volatile("cp.async.commit_group;" ::: "memory");
}
__device__ __forceinline__ void cp_wait1() {
    asm volatile("cp.async.wait_group 1;" ::: "memory");
}

template<typename T> __device__ __forceinline__ void store2(T* p, float x, float y);
template<> __device__ __forceinline__ void store2<float>(float* p, float x, float y) {
    *reinterpret_cast<float2*>(p) = make_float2(x, y);
}
template<> __device__ __forceinline__ void store2<__half>(__half* p, float x, float y) {
    *reinterpret_cast<__half2*>(p) = __floats2half2_rn(x, y);
}

// ---------------- f32 -> f16 conversion pass (8 elems/thread) ----------------
__global__ void f32_to_f16(const float4* __restrict__ src, uint4* __restrict__ dst, int n8) {
    int i = blockIdx.x * blockDim.x + threadIdx.x;
    if (i < n8) {
        float4 a = src[i * 2], b = src[i * 2 + 1];
        uint4 o;
        o.x = h2_to_u32(__floats2half2_rn(a.x, a.y));
        o.y = h2_to_u32(__floats2half2_rn(a.z, a.w));
        o.z = h2_to_u32(__floats2half2_rn(b.x, b.y));
        o.w = h2_to_u32(__floats2half2_rn(b.z, b.w));
        dst[i] = o;
    }
}

// ============ pipelined fp16 GEMM: C[M,N] = A[M,256] @ B[N,256]^T + bias ============
// CTA 128x128, 8 warps (4 row x 2 col), warp tile 32x64, mma m16n8k16.
// 3-stage cp.async; ldmatrix.x4 fragments.
template<typename OutT>
__global__ __launch_bounds__(256, 2)
void pipe_gemm_h(const __half* __restrict__ A, const __half* __restrict__ Bw,
                 const float* __restrict__ bias, OutT* __restrict__ C, int M, int N) {
    constexpr int BM = 128;
    constexpr int BN = 128;
    constexpr int BK = 32;                 // K elements per chunk (64B rows)
    constexpr int LD = 40;                 // halves per row (80B: 16B-aligned)
    constexpr int NCHUNK = DMOD / BK;      // 8
    constexpr int ASZ = BM * LD;           // halves
    constexpr int BSZ = BN * LD;
    constexpr int SSZ = ASZ + BSZ;

    extern __shared__ __half smh[];
    const uint32_t smem_u32 = (uint32_t)__cvta_generic_to_shared(smh);

    const int tid = threadIdx.x;
    const int wid = tid >> 5;
    const int lane = tid & 31;
    const int wm = wid & 3;
    const int wn = wid >> 2;
    const int bm = blockIdx.y * BM;
    const int bn = blockIdx.x * BN;
    const int lq = lane >> 2;
    const int lr = lane & 3;

    // ldmatrix lane offsets (in halves)
    const int arow_l = wm * 32 + (lane & 15);
    const int acol_l = (lane >> 4) << 3;
    const int brow_l = wn * 64 + (lane & 7) + ((lane >> 4) << 3);
    const int bcol_l = ((lane >> 3) & 1) << 3;

    // copy coords: 4 x 16B per thread per stage (2 A-rows + 2 B-rows)
    const int r0 = tid >> 2;               // 0..63
    const int f8 = (tid & 3) * 8;          // half offset in row
    const __half* abase = A + (size_t)(bm + r0) * DMOD + f8;
    const __half* bbase = Bw + (size_t)(bn + r0) * DMOD + f8;
    uint32_t asz[2];
#pragma unroll
    for (int i = 0; i < 2; i++) asz[i] = (bm + r0 + 64 * i) < M ? 16u : 0u;

    auto issue_stage = [&](int buf, int k0) {
        const uint32_t sb = smem_u32 + (uint32_t)(buf * SSZ) * 2u;
#pragma unroll
        for (int i = 0; i < 2; i++)
            cp_async16(sb + (uint32_t)((r0 + 64 * i) * LD + f8) * 2u,
                       abase + k0 + (size_t)(64 * i) * DMOD, asz[i]);
#pragma unroll
        for (int i = 0; i < 2; i++)
            cp_async16(sb + (uint32_t)(ASZ + (r0 + 64 * i) * LD + f8) * 2u,
                       bbase + k0 + (size_t)(64 * i) * DMOD, 16u);
    };

    float acc[2][8][4];
#pragma unroll
    for (int i = 0; i < 2; i++)
#pragma unroll
        for (int j = 0; j < 8; j++)
#pragma unroll
            for (int r = 0; r < 4; r++) acc[i][j][r] = 0.0f;

    issue_stage(0, 0); cp_commit();
    issue_stage(1, BK); cp_commit();

    for (int c = 0; c < NCHUNK; c++) {
        cp_wait1();
        __syncthreads();
        if (c + 2 < NCHUNK) issue_stage((c + 2) % 3, (c + 2) * BK);
        cp_commit();

        const uint32_t As_u = smem_u32 + (uint32_t)((c % 3) * SSZ) * 2u;
        const uint32_t Bs_u = As_u + (uint32_t)ASZ * 2u;
#pragma unroll
        for (int ks = 0; ks < 2; ks++) {           // two k16 steps per chunk
            const int kk = ks * 16;
            uint32_t a[2][4], b[4][4];
#pragma unroll
            for (int mi = 0; mi < 2; mi++)
                ldsm4(a[mi][0], a[mi][1], a[mi][2], a[mi][3],
                      As_u + (uint32_t)((arow_l + mi * 16) * LD + kk + acol_l) * 2u);
#pragma unroll
            for (int nb = 0; nb < 4; nb++)
                ldsm4(b[nb][0], b[nb][1], b[nb][2], b[nb][3],
                      Bs_u + (uint32_t)((brow_l + nb * 16) * LD + kk + bcol_l) * 2u);
#pragma unroll
            for (int mi = 0; mi < 2; mi++)
#pragma unroll
                for (int nb = 0; nb < 4; nb++) {
                    mma16n8k16h(acc[mi][nb * 2 + 0], a[mi], &b[nb][0]);
                    mma16n8k16h(acc[mi][nb * 2 + 1], a[mi], &b[nb][2]);
                }
        }
    }

    // epilogue
#pragma unroll
    for (int mi = 0; mi < 2; mi++) {
        const int row0 = bm + wm * 32 + mi * 16 + lq;
#pragma unroll
        for (int ni = 0; ni < 8; ni++) {
            const int col = bn + wn * 64 + ni * 8 + lr * 2;
            const float bz0 = bias[col], bz1 = bias[col + 1];
            if (row0 < M)
                store2(C + (size_t)row0 * N + col,
                       acc[mi][ni][0] + bz0, acc[mi][ni][1] + bz1);
            if (row0 + 8 < M)
                store2(C + (size_t)(row0 + 8) * N + col,
                       acc[mi][ni][2] + bz0, acc[mi][ni][3] + bz1);
        }
    }
}

// ============ [off|attn] projection: (query+qpos) @ [W_off; W_attn]^T + bias ============
// tf32 path (small N; fuses the query+query_pos add in the loader).
__global__ __launch_bounds__(384, 1)
void oa_gemm(const float* __restrict__ A, const float* __restrict__ A2,
             const float* __restrict__ B1, const float* __restrict__ B2,
             const float* __restrict__ bias1, const float* __restrict__ bias2,
             float* __restrict__ C, int M) {
    constexpr int BM = 128, BN = 96, BK = 32, LD = 36;
    constexpr int NT = 384;
    constexpr int AITER = 3;
    constexpr int BITER = 2;

    __shared__ float As[BM * LD];
    __shared__ float Bs[BN * LD];

    const int tid = threadIdx.x;
    const int wid = tid >> 5;
    const int lane = tid & 31;
    const int wm = wid & 3;
    const int wn = wid >> 2;
    const int bm = blockIdx.y * BM;
    const int lq = lane >> 2;
    const int lr = lane & 3;

    const int arow_l = wm * 32 + (lane & 15);
    const int acol_l = (lane >> 4) << 2;
    const int brow_l = wn * 32 + (lane & 7) + ((lane >> 4) << 3);
    const int bcol_l = ((lane >> 3) & 1) << 2;
    const uint32_t As_u = (uint32_t)__cvta_generic_to_shared(As);
    const uint32_t Bs_u = (uint32_t)__cvta_generic_to_shared(Bs);

    float acc[2][4][4];
#pragma unroll
    for (int i = 0; i < 2; i++)
#pragma unroll
        for (int j = 0; j < 4; j++)
#pragma unroll
            for (int r = 0; r < 4; r++) acc[i][j][r] = 0.0f;

    float4 ra[AITER], rb[BITER];
    auto load_tiles = [&](int k0) {
#pragma unroll
        for (int i = 0; i < AITER; i++) {
            int idx = tid + i * NT;
            if (idx < BM * 8) {
                int row = idx >> 3, f = idx & 7;
                int gr = bm + row; gr = gr < M ? gr : M - 1;
                float4 v = *reinterpret_cast<const float4*>(A + (size_t)gr * DMOD + k0 + f * 4);
                float4 w = *reinterpret_cast<const float4*>(A2 + (size_t)gr * DMOD + k0 + f * 4);
                v.x += w.x; v.y += w.y; v.z += w.z; v.w += w.w;
                ra[i] = v;
            }
        }
#pragma unroll
        for (int i = 0; i < BITER; i++) {
            int idx = tid + i * NT;
            int row = idx >> 3, f = idx & 7;
            const float* bp = row < 64 ? B1 + (size_t)row * DMOD
                                       : B2 + (size_t)(row - 64) * DMOD;
            rb[i] = *reinterpret_cast<const float4*>(bp + k0 + f * 4);
        }
    };
    auto store_smem = [&]() {
#pragma unroll
        for (int i = 0; i < AITER; i++) {
            int idx = tid + i * NT;
            if (idx < BM * 8) {
                int row = idx >> 3, f = idx & 7;
                uint4 t = make_uint4(tf32_rna(ra[i].x), tf32_rna(ra[i].y),
                                     tf32_rna(ra[i].z), tf32_rna(ra[i].w));
                *reinterpret_cast<uint4*>(&As[row * LD + f * 4]) = t;
            }
        }
#pragma unroll
        for (int i = 0; i < BITER; i++) {
            int idx = tid + i * NT;
            int row = idx >> 3, f = idx & 7;
            uint4 t = make_uint4(tf32_rna(rb[i].x), tf32_rna(rb[i].y),
                                 tf32_rna(rb[i].z), tf32_rna(rb[i].w));
            *reinterpret_cast<uint4*>(&Bs[row * LD + f * 4]) = t;
        }
    };

    load_tiles(0);
    for (int c = 0; c < DMOD / BK; c++) {
        store_smem();
        __syncthreads();
        if (c < DMOD / BK - 1) load_tiles((c + 1) * BK);
#pragma unroll
        for (int ks = 0; ks < 4; ks++) {
            const int kk = ks * 8;
            uint32_t a[2][4], bA[4], bB[4];
#pragma unroll
            for (int mi = 0; mi < 2; mi++)
                ldsm4(a[mi][0], a[mi][1], a[mi][2], a[mi][3],
                      As_u + (uint32_t)((arow_l + mi * 16) * LD + kk + acol_l) * 4u);
            ldsm4(bA[0], bA[1], bA[2], bA[3],
                  Bs_u + (uint32_t)(brow_l * LD + kk + bcol_l) * 4u);
            ldsm4(bB[0], bB[1], bB[2], bB[3],
                  Bs_u + (uint32_t)((brow_l + 16) * LD + kk + bcol_l) * 4u);
#pragma unroll
            for (int mi = 0; mi < 2; mi++) {
                mma16n8k8(acc[mi][0], a[mi], &bA[0]);
                mma16n8k8(acc[mi][1], a[mi], &bA[2]);
                mma16n8k8(acc[mi][2], a[mi], &bB[0]);
                mma16n8k8(acc[mi][3], a[mi], &bB[2]);
            }
        }
        __syncthreads();
    }

#pragma unroll
    for (int mi = 0; mi < 2; mi++) {
        const int row0 = bm + wm * 32 + mi * 16 + lq;
#pragma unroll
        for (int ni = 0; ni < 4; ni++) {
            const int col = wn * 32 + ni * 8 + lr * 2;
            const float bz0 = col < 64 ? bias1[col] : bias2[col - 64];
            const float bz1 = (col + 1) < 64 ? bias1[col + 1] : bias2[col + 1 - 64];
            if (row0 < M) {
                float2 o = make_float2(acc[mi][ni][0] + bz0, acc[mi][ni][1] + bz1);
                *reinterpret_cast<float2*>(C + (size_t)row0 * 96 + col) = o;
            }
            if (row0 + 8 < M) {
                float2 o = make_float2(acc[mi][ni][2] + bz0, acc[mi][ni][3] + bz1);
                *reinterpret_cast<float2*>(C + (size_t)(row0 + 8) * 96 + col) = o;
            }
        }
    }
}

// ---------------- sampler: scalar phase + fp16 gather phase ----------------
__global__ __launch_bounds__(256)
void sample_kernel(const float* __restrict__ refpts) {
    __shared__ int2 s_pc[256 * 4];

    const int tid = threadIdx.x;
    const int q0 = blockIdx.x * GQ;
    const int qi = tid >> 5;
    const int h = (tid >> 2) & 7;
    const int p = tid & 3;
    const int q = q0 + qi;

    const float refx = refpts[q * 2 + 0];
    const float refy = refpts[q * 2 + 1];
    const float* row = g_oa + (size_t)q * 96;
    const float lg = row[64 + h * 4 + p];
    const float ox = row[h * 8 + p * 2 + 0];
    const float oy = row[h * 8 + p * 2 + 1];

    float mx = lg;
    mx = fmaxf(mx, __shfl_xor_sync(0xFFFFFFFFu, mx, 1));
    mx = fmaxf(mx, __shfl_xor_sync(0xFFFFFFFFu, mx, 2));
    float e = expf(lg - mx);
    float s = e;
    s += __shfl_xor_sync(0xFFFFFFFFu, s, 1);
    s += __shfl_xor_sync(0xFFFFFFFFu, s, 2);
    const float ap = e / s;

    const float x = (refx + ox * (1.0f / WSP)) * WSP - 0.5f;
    const float y = (refy + oy * (1.0f / HSP)) * HSP - 0.5f;
    const float x0f = floorf(x), y0f = floorf(y);
    const int x0 = (int)x0f, y0 = (int)y0f;
    const float lw = x - x0f, lh = y - y0f;
    const int x1 = x0 + 1, y1 = y0 + 1;

    const float wc[4] = { (1.0f - lh) * (1.0f - lw), (1.0f - lh) * lw,
                          lh * (1.0f - lw),          lh * lw };
    const int xs[4] = { x0, x1, x0, x1 };
    const int ys[4] = { y0, y0, y1, y1 };
#pragma unroll
    for (int c = 0; c < 4; c++) {
        const bool v = (xs[c] >= 0) & (xs[c] < WSP) & (ys[c] >= 0) & (ys[c] < HSP);
        const float w = v ? ap * wc[c] : 0.0f;
        const int idx = v ? (ys[c] * WSP + xs[c]) : 0;
        s_pc[tid * 4 + c] = make_int2(idx, __float_as_int(w));
    }
    __syncthreads();

    const int wid = tid >> 5, lane = tid & 31;
    __half* outp = g_sampled + (size_t)(q0 + wid) * DMOD + lane;
#pragma unroll
    for (int hh = 0; hh < NH; hh++) {
        const __half* vb = g_value + hh * DH + lane;
        const int base = (wid * 32 + hh * 4) * 4;
        float acc0 = 0.0f, acc1 = 0.0f;
#pragma unroll
        for (int pc = 0; pc < 16; pc += 2) {
            int2 a = s_pc[base + pc];
            int2 b = s_pc[base + pc + 1];
            acc0 += __int_as_float(a.y) * __half2float(vb[(size_t)a.x * DMOD]);
            acc1 += __int_as_float(b.y) * __half2float(vb[(size_t)b.x * DMOD]);
        }
        outp[hh * DH] = __float2half_rn(acc0 + acc1);
    }
}

// ---------------- launch ----------------
extern "C" void kernel_launch(void* const* d_in, const int* in_sizes, int n_in,
                              void* d_out, int out_size) {
    const float* query  = (const float*)d_in[0];
    const float* qpos   = (const float*)d_in[1];
    const float* refpts = (const float*)d_in[2];
    const float* inp    = (const float*)d_in[3];
    const float* Wv     = (const float*)d_in[4];
    const float* bv     = (const float*)d_in[5];
    const float* Woff   = (const float*)d_in[6];
    const float* boff   = (const float*)d_in[7];
    const float* Wattn  = (const float*)d_in[8];
    const float* battn  = (const float*)d_in[9];
    const float* Wout   = (const float*)d_in[10];
    const float* bout   = (const float*)d_in[11];
    float* out = (float*)d_out;

    __half *p_val, *p_samp, *p_inp, *p_wv, *p_wout;
    float* p_oa;
    cudaGetSymbolAddress((void**)&p_val, g_value);
    cudaGetSymbolAddress((void**)&p_oa, g_oa);
    cudaGetSymbolAddress((void**)&p_samp, g_sampled);
    cudaGetSymbolAddress((void**)&p_inp, g_inp);
    cudaGetSymbolAddress((void**)&p_wv, g_wv);
    cudaGetSymbolAddress((void**)&p_wout, g_wout);

    const int gy = (LQ + 127) / 128;  // 313
    const int SMEM_PIPE = 3 * (128 * 40 + 128 * 40) * 2;  // 61440
    cudaFuncSetAttribute(pipe_gemm_h<__half>, cudaFuncAttributeMaxDynamicSharedMemorySize, SMEM_PIPE);
    cudaFuncSetAttribute(pipe_gemm_h<float>,  cudaFuncAttributeMaxDynamicSharedMemorySize, SMEM_PIPE);

    // 0. convert GEMM operands to fp16 once
    {
        int n8 = LQ * DMOD / 8;
        f32_to_f16<<<(n8 + 255) / 256, 256>>>((const float4*)inp, (uint4*)p_inp, n8);
        int w8 = DMOD * DMOD / 8;
        f32_to_f16<<<(w8 + 255) / 256, 256>>>((const float4*)Wv, (uint4*)p_wv, w8);
        f32_to_f16<<<(w8 + 255) / 256, 256>>>((const float4*)Wout, (uint4*)p_wout, w8);
    }

    // 1. value = input_flatten @ W_value^T + b_value  (fp16 out)
    pipe_gemm_h<__half><<<dim3(2, gy), 256, SMEM_PIPE>>>(p_inp, p_wv, bv, p_val, LQ, DMOD);

    // 2. [off | attn] = (query+query_pos) @ [W_off; W_attn]^T + bias
    oa_gemm<<<dim3(1, gy), 384>>>(query, qpos, Woff, Wattn, boff, battn, p_oa, LQ);

    // 3. fused softmax + bilinear sampling (fp16 gathers, fp16 out)
    sample_kernel<<<LQ / GQ, 256>>>(refpts);

    // 4. out = sampled @ W_out^T + b_out
    pipe_gemm_h<float><<<dim3(2, gy), 256, SMEM_PIPE>>>(p_samp, p_wout, bout, out, LQ, DMOD);
}

// round 11
// speedup vs baseline: 1.4627x; 1.1884x over previous
#include <cuda_runtime.h>
#include <cuda_fp16.h>
#include <cstdint>
#include <math.h>

#define LQ   40000
#define DMOD 256
#define NH   8
#define NP   4
#define DH   32
#define HSP  200
#define WSP  200
#define GQ   8

// ---------------- scratch (no allocations allowed) ----------------
__device__ __half g_value[LQ * DMOD];     // value projection (fp16)
__device__ float  g_oa[LQ * 128];         // [off(64) | attn(32) | pad(32)] per query
__device__ __half g_sampled[LQ * DMOD];   // sampled output (fp16)
__device__ __half g_inp[LQ * DMOD];       // fp16 input_flatten
__device__ __half g_q16[LQ * DMOD];       // fp16 (query + query_pos)
__device__ __half g_wv[DMOD * DMOD];      // fp16 W_value
__device__ __half g_wout[DMOD * DMOD];    // fp16 W_out
__device__ __half g_woa[128 * DMOD];      // fp16 [W_off; W_attn; zeros]
__device__ float  g_boa[128];             // padded [b_off; b_attn; zeros]

// ---------------- helpers ----------------
__device__ __forceinline__ uint32_t h2_to_u32(__half2 h) {
    uint32_t u;
    memcpy(&u, &h, 4);
    return u;
}
__device__ __forceinline__ uint4 pack8(float4 a, float4 b) {
    uint4 o;
    o.x = h2_to_u32(__floats2half2_rn(a.x, a.y));
    o.y = h2_to_u32(__floats2half2_rn(a.z, a.w));
    o.z = h2_to_u32(__floats2half2_rn(b.x, b.y));
    o.w = h2_to_u32(__floats2half2_rn(b.z, b.w));
    return o;
}
__device__ __forceinline__ void mma16n8k16h(float* c, const uint32_t* a, const uint32_t* b) {
    asm volatile(
        "mma.sync.aligned.m16n8k16.row.col.f32.f16.f16.f32 "
        "{%0,%1,%2,%3}, {%4,%5,%6,%7}, {%8,%9}, {%0,%1,%2,%3};"
        : "+f"(c[0]), "+f"(c[1]), "+f"(c[2]), "+f"(c[3])
        : "r"(a[0]), "r"(a[1]), "r"(a[2]), "r"(a[3]), "r"(b[0]), "r"(b[1]));
}
__device__ __forceinline__ void ldsm4(uint32_t& r0, uint32_t& r1, uint32_t& r2,
                                      uint32_t& r3, uint32_t addr) {
    asm volatile("ldmatrix.sync.aligned.m8n8.x4.shared.b16 {%0,%1,%2,%3}, [%4];"
                 : "=r"(r0), "=r"(r1), "=r"(r2), "=r"(r3) : "r"(addr));
}
__device__ __forceinline__ void cp_async16(uint32_t dst, const void* src, uint32_t sz) {
    asm volatile("cp.async.cg.shared.global [%0], [%1], 16, %2;"
                 :: "r"(dst), "l"(src), "r"(sz));
}
__device__ __forceinline__ void cp_commit() {
    asm volatile("cp.async.commit_group;" ::: "memory");
}
__device__ __forceinline__ void cp_wait1() {
    asm volatile("cp.async.wait_group 1;" ::: "memory");
}

// ---------------- fused conversion: inp, (q+qpos), Wv, Wout -> fp16 ----------------
#define N8U (LQ * DMOD / 8)     // 1,280,000 units of 8 floats
#define W8U (DMOD * DMOD / 8)   // 8,192
__global__ void conv_fused(const float4* __restrict__ query, const float4* __restrict__ qpos,
                           const float4* __restrict__ inp, const float4* __restrict__ wv,
                           const float4* __restrict__ wout) {
    int i = blockIdx.x * blockDim.x + threadIdx.x;
    if (i < N8U) {
        float4 a = inp[i * 2], b = inp[i * 2 + 1];
        reinterpret_cast<uint4*>(g_inp)[i] = pack8(a, b);
    } else if (i < 2 * N8U) {
        int o = i - N8U;
        float4 a = query[o * 2], b = query[o * 2 + 1];
        float4 c = qpos[o * 2],  d = qpos[o * 2 + 1];
        a.x += c.x; a.y += c.y; a.z += c.z; a.w += c.w;
        b.x += d.x; b.y += d.y; b.z += d.z; b.w += d.w;
        reinterpret_cast<uint4*>(g_q16)[o] = pack8(a, b);
    } else if (i < 2 * N8U + W8U) {
        int o = i - 2 * N8U;
        reinterpret_cast<uint4*>(g_wv)[o] = pack8(wv[o * 2], wv[o * 2 + 1]);
    } else if (i < 2 * N8U + 2 * W8U) {
        int o = i - 2 * N8U - W8U;
        reinterpret_cast<uint4*>(g_wout)[o] = pack8(wout[o * 2], wout[o * 2 + 1]);
    }
}

// ---------------- pad [W_off; W_attn; 0] -> g_woa (fp16) + g_boa ----------------
__global__ void pad_woa(const float4* __restrict__ woff, const float4* __restrict__ wattn,
                        const float* __restrict__ boff, const float* __restrict__ battn) {
    if (blockIdx.x < 16) {
        int i = blockIdx.x * 256 + threadIdx.x;   // unit of 8 floats; 32 units/row
        int row = i >> 5, c8 = i & 31;
        float4 a, b;
        if (row < 64)      { a = woff[row * 64 + c8 * 2];          b = woff[row * 64 + c8 * 2 + 1]; }
        else if (row < 96) { a = wattn[(row - 64) * 64 + c8 * 2];  b = wattn[(row - 64) * 64 + c8 * 2 + 1]; }
        else               { a = make_float4(0, 0, 0, 0); b = a; }
        reinterpret_cast<uint4*>(g_woa)[i] = pack8(a, b);
    } else {
        int t = threadIdx.x;
        if (t < 128)
            g_boa[t] = t < 64 ? boff[t] : (t < 96 ? battn[t - 64] : 0.0f);
    }
}

// ============ shared fp16 GEMM body: C[M,N](bn tile) = A[M,256] @ B[.,256]^T + bias ============
// CTA tile 128x128, 8 warps (4 row x 2 col), warp tile 32x64, m16n8k16.
__device__ __forceinline__ void gemm_body(const __half* __restrict__ A,
                                          const __half* __restrict__ B,
                                          const float* __restrict__ bias,
                                          __half* __restrict__ Ch, float* __restrict__ Cf,
                                          int bn, int N, int M) {
    constexpr int BM = 128, BK = 32, LD = 40;
    constexpr int NCHUNK = DMOD / BK;      // 8
    constexpr int ASZ = BM * LD;
    constexpr int SSZ = 2 * ASZ;

    extern __shared__ __half smh[];
    const uint32_t smem_u32 = (uint32_t)__cvta_generic_to_shared(smh);

    const int tid = threadIdx.x;
    const int wid = tid >> 5;
    const int lane = tid & 31;
    const int wm = wid & 3;
    const int wn = wid >> 2;
    const int bm = blockIdx.y * BM;
    const int lq = lane >> 2;
    const int lr = lane & 3;

    const int arow_l = wm * 32 + (lane & 15);
    const int acol_l = (lane >> 4) << 3;
    const int brow_l = wn * 64 + (lane & 7) + ((lane >> 4) << 3);
    const int bcol_l = ((lane >> 3) & 1) << 3;

    const int r0 = tid >> 2;
    const int f8 = (tid & 3) * 8;
    const __half* abase = A + (size_t)(bm + r0) * DMOD + f8;
    const __half* bbase = B + (size_t)(bn + r0) * DMOD + f8;
    uint32_t asz[2];
#pragma unroll
    for (int i = 0; i < 2; i++) asz[i] = (bm + r0 + 64 * i) < M ? 16u : 0u;

    auto issue_stage = [&](int buf, int k0) {
        const uint32_t sb = smem_u32 + (uint32_t)(buf * SSZ) * 2u;
#pragma unroll
        for (int i = 0; i < 2; i++)
            cp_async16(sb + (uint32_t)((r0 + 64 * i) * LD + f8) * 2u,
                       abase + k0 + (size_t)(64 * i) * DMOD, asz[i]);
#pragma unroll
        for (int i = 0; i < 2; i++)
            cp_async16(sb + (uint32_t)(ASZ + (r0 + 64 * i) * LD + f8) * 2u,
                       bbase + k0 + (size_t)(64 * i) * DMOD, 16u);
    };

    float acc[2][8][4];
#pragma unroll
    for (int i = 0; i < 2; i++)
#pragma unroll
        for (int j = 0; j < 8; j++)
#pragma unroll
            for (int r = 0; r < 4; r++) acc[i][j][r] = 0.0f;

    issue_stage(0, 0); cp_commit();
    issue_stage(1, BK); cp_commit();

    for (int c = 0; c < NCHUNK; c++) {
        cp_wait1();
        __syncthreads();
        if (c + 2 < NCHUNK) issue_stage((c + 2) % 3, (c + 2) * BK);
        cp_commit();

        const uint32_t As_u = smem_u32 + (uint32_t)((c % 3) * SSZ) * 2u;
        const uint32_t Bs_u = As_u + (uint32_t)ASZ * 2u;
#pragma unroll
        for (int ks = 0; ks < 2; ks++) {
            const int kk = ks * 16;
            uint32_t a[2][4], b[4][4];
#pragma unroll
            for (int mi = 0; mi < 2; mi++)
                ldsm4(a[mi][0], a[mi][1], a[mi][2], a[mi][3],
                      As_u + (uint32_t)((arow_l + mi * 16) * LD + kk + acol_l) * 2u);
#pragma unroll
            for (int nb = 0; nb < 4; nb++)
                ldsm4(b[nb][0], b[nb][1], b[nb][2], b[nb][3],
                      Bs_u + (uint32_t)((brow_l + nb * 16) * LD + kk + bcol_l) * 2u);
#pragma unroll
            for (int mi = 0; mi < 2; mi++)
#pragma unroll
                for (int nb = 0; nb < 4; nb++) {
                    mma16n8k16h(acc[mi][nb * 2 + 0], a[mi], &b[nb][0]);
                    mma16n8k16h(acc[mi][nb * 2 + 1], a[mi], &b[nb][2]);
                }
        }
    }

#pragma unroll
    for (int mi = 0; mi < 2; mi++) {
        const int row0 = bm + wm * 32 + mi * 16 + lq;
#pragma unroll
        for (int ni = 0; ni < 8; ni++) {
            const int col = bn + wn * 64 + ni * 8 + lr * 2;
            const float bz0 = bias[col], bz1 = bias[col + 1];
            if (Cf) {
                if (row0 < M)
                    *reinterpret_cast<float2*>(Cf + (size_t)row0 * N + col) =
                        make_float2(acc[mi][ni][0] + bz0, acc[mi][ni][1] + bz1);
                if (row0 + 8 < M)
                    *reinterpret_cast<float2*>(Cf + (size_t)(row0 + 8) * N + col) =
                        make_float2(acc[mi][ni][2] + bz0, acc[mi][ni][3] + bz1);
            } else {
                if (row0 < M)
                    *reinterpret_cast<__half2*>(Ch + (size_t)row0 * N + col) =
                        __floats2half2_rn(acc[mi][ni][0] + bz0, acc[mi][ni][1] + bz1);
                if (row0 + 8 < M)
                    *reinterpret_cast<__half2*>(Ch + (size_t)(row0 + 8) * N + col) =
                        __floats2half2_rn(acc[mi][ni][2] + bz0, acc[mi][ni][3] + bz1);
            }
        }
    }
}

// ---- fused value + oa GEMM: blockIdx.x<2 -> value tiles, ==2 -> oa tile ----
__global__ __launch_bounds__(256, 2)
void valoa_gemm(const float* __restrict__ bv) {
    if (blockIdx.x < 2)
        gemm_body(g_inp, g_wv, bv, g_value, nullptr, blockIdx.x * 128, DMOD, LQ);
    else
        gemm_body(g_q16, g_woa, g_boa, nullptr, g_oa, 0, 128, LQ);
}

// ---- output GEMM: out = sampled @ W_out^T + b_out ----
__global__ __launch_bounds__(256, 2)
void out_gemm(const float* __restrict__ bout, float* __restrict__ out) {
    gemm_body(g_sampled, g_wout, bout, nullptr, out, blockIdx.x * 128, DMOD, LQ);
}

// ---------------- sampler: scalar phase + fp16 gather phase ----------------
__global__ __launch_bounds__(256)
void sample_kernel(const float* __restrict__ refpts) {
    __shared__ int2 s_pc[256 * 4];

    const int tid = threadIdx.x;
    const int q0 = blockIdx.x * GQ;
    const int qi = tid >> 5;
    const int h = (tid >> 2) & 7;
    const int p = tid & 3;
    const int q = q0 + qi;

    const float refx = refpts[q * 2 + 0];
    const float refy = refpts[q * 2 + 1];
    const float* row = g_oa + (size_t)q * 128;
    const float lg = row[64 + h * 4 + p];
    const float ox = row[h * 8 + p * 2 + 0];
    const float oy = row[h * 8 + p * 2 + 1];

    float mx = lg;
    mx = fmaxf(mx, __shfl_xor_sync(0xFFFFFFFFu, mx, 1));
    mx = fmaxf(mx, __shfl_xor_sync(0xFFFFFFFFu, mx, 2));
    float e = expf(lg - mx);
    float s = e;
    s += __shfl_xor_sync(0xFFFFFFFFu, s, 1);
    s += __shfl_xor_sync(0xFFFFFFFFu, s, 2);
    const float ap = e / s;

    const float x = (refx + ox * (1.0f / WSP)) * WSP - 0.5f;
    const float y = (refy + oy * (1.0f / HSP)) * HSP - 0.5f;
    const float x0f = floorf(x), y0f = floorf(y);
    const int x0 = (int)x0f, y0 = (int)y0f;
    const float lw = x - x0f, lh = y - y0f;
    const int x1 = x0 + 1, y1 = y0 + 1;

    const float wc[4] = { (1.0f - lh) * (1.0f - lw), (1.0f - lh) * lw,
                          lh * (1.0f - lw),          lh * lw };
    const int xs[4] = { x0, x1, x0, x1 };
    const int ys[4] = { y0, y0, y1, y1 };
#pragma unroll
    for (int c = 0; c < 4; c++) {
        const bool v = (xs[c] >= 0) & (xs[c] < WSP) & (ys[c] >= 0) & (ys[c] < HSP);
        const float w = v ? ap * wc[c] : 0.0f;
        const int idx = v ? (ys[c] * WSP + xs[c]) : 0;
        s_pc[tid * 4 + c] = make_int2(idx, __float_as_int(w));
    }
    __syncthreads();

    const int wid = tid >> 5, lane = tid & 31;
    __half* outp = g_sampled + (size_t)(q0 + wid) * DMOD + lane;
#pragma unroll
    for (int hh = 0; hh < NH; hh++) {
        const __half* vb = g_value + hh * DH + lane;
        const int base = (wid * 32 + hh * 4) * 4;
        float acc0 = 0.0f, acc1 = 0.0f;
#pragma unroll
        for (int pc = 0; pc < 16; pc += 2) {
            int2 a = s_pc[base + pc];
            int2 b = s_pc[base + pc + 1];
            acc0 += __int_as_float(a.y) * __half2float(vb[(size_t)a.x * DMOD]);
            acc1 += __int_as_float(b.y) * __half2float(vb[(size_t)b.x * DMOD]);
        }
        outp[hh * DH] = __float2half_rn(acc0 + acc1);
    }
}

// ---------------- launch ----------------
extern "C" void kernel_launch(void* const* d_in, const int* in_sizes, int n_in,
                              void* d_out, int out_size) {
    const float* query  = (const float*)d_in[0];
    const float* qpos   = (const float*)d_in[1];
    const float* refpts = (const float*)d_in[2];
    const float* inp    = (const float*)d_in[3];
    const float* Wv     = (const float*)d_in[4];
    const float* bv     = (const float*)d_in[5];
    const float* Woff   = (const float*)d_in[6];
    const float* boff   = (const float*)d_in[7];
    const float* Wattn  = (const float*)d_in[8];
    const float* battn  = (const float*)d_in[9];
    const float* Wout   = (const float*)d_in[10];
    const float* bout   = (const float*)d_in[11];
    float* out = (float*)d_out;

    const int gy = (LQ + 127) / 128;  // 313
    const int SMEM_PIPE = 3 * (2 * 128 * 40) * 2;  // 61440
    cudaFuncSetAttribute(valoa_gemm, cudaFuncAttributeMaxDynamicSharedMemorySize, SMEM_PIPE);
    cudaFuncSetAttribute(out_gemm,   cudaFuncAttributeMaxDynamicSharedMemorySize, SMEM_PIPE);

    // 0. conversions: inp, q+qpos, Wv, Wout -> fp16 ; pad [Woff;Wattn] -> g_woa
    {
        int total = 2 * N8U + 2 * W8U;
        conv_fused<<<(total + 255) / 256, 256>>>(
            (const float4*)query, (const float4*)qpos, (const float4*)inp,
            (const float4*)Wv, (const float4*)Wout);
        pad_woa<<<17, 256>>>((const float4*)Woff, (const float4*)Wattn, boff, battn);
    }

    // 1. fused: value projection (x<2) + [off|attn] projection (x==2)
    valoa_gemm<<<dim3(3, gy), 256, SMEM_PIPE>>>(bv);

    // 2. fused softmax + bilinear sampling (fp16 gathers, fp16 out)
    sample_kernel<<<LQ / GQ, 256>>>(refpts);

    // 3. out = sampled @ W_out^T + b_out
    out_gemm<<<dim3(2, gy), 256, SMEM_PIPE>>>(bout, out);
}

// round 12
// speedup vs baseline: 1.6447x; 1.1244x over previous
#include <cuda_runtime.h>
#include <cuda_fp16.h>
#include <cstdint>
#include <math.h>

#define LQ   40000
#define DMOD 256
#define NH   8
#define NP   4
#define DH   32
#define HSP  200
#define WSP  200
#define GQ   8

// ---------------- scratch (no allocations allowed) ----------------
__device__ __half g_value[LQ * DMOD];     // value projection (fp16)
__device__ float  g_oa[LQ * 128];         // [off(64) | attn(32) | pad(32)] per query
__device__ __half g_sampled[LQ * DMOD];   // sampled output (fp16)
__device__ __half g_inp[LQ * DMOD];       // fp16 input_flatten
__device__ __half g_q16[LQ * DMOD];       // fp16 (query + query_pos)
__device__ __half g_wv[DMOD * DMOD];      // fp16 W_value
__device__ __half g_wout[DMOD * DMOD];    // fp16 W_out
__device__ __half g_woa[128 * DMOD];      // fp16 [W_off; W_attn; zeros]
__device__ float  g_boa[128];             // padded [b_off; b_attn; zeros]

// ---------------- helpers ----------------
__device__ __forceinline__ uint32_t h2_to_u32(__half2 h) {
    uint32_t u;
    memcpy(&u, &h, 4);
    return u;
}
__device__ __forceinline__ uint4 pack8(float4 a, float4 b) {
    uint4 o;
    o.x = h2_to_u32(__floats2half2_rn(a.x, a.y));
    o.y = h2_to_u32(__floats2half2_rn(a.z, a.w));
    o.z = h2_to_u32(__floats2half2_rn(b.x, b.y));
    o.w = h2_to_u32(__floats2half2_rn(b.z, b.w));
    return o;
}
__device__ __forceinline__ void mma16n8k16h(float* c, const uint32_t* a, const uint32_t* b) {
    asm volatile(
        "mma.sync.aligned.m16n8k16.row.col.f32.f16.f16.f32 "
        "{%0,%1,%2,%3}, {%4,%5,%6,%7}, {%8,%9}, {%0,%1,%2,%3};"
        : "+f"(c[0]), "+f"(c[1]), "+f"(c[2]), "+f"(c[3])
        : "r"(a[0]), "r"(a[1]), "r"(a[2]), "r"(a[3]), "r"(b[0]), "r"(b[1]));
}
__device__ __forceinline__ void ldsm4(uint32_t& r0, uint32_t& r1, uint32_t& r2,
                                      uint32_t& r3, uint32_t addr) {
    asm volatile("ldmatrix.sync.aligned.m8n8.x4.shared.b16 {%0,%1,%2,%3}, [%4];"
                 : "=r"(r0), "=r"(r1), "=r"(r2), "=r"(r3) : "r"(addr));
}
__device__ __forceinline__ void cp_async16(uint32_t dst, const void* src, uint32_t sz) {
    asm volatile("cp.async.cg.shared.global [%0], [%1], 16, %2;"
                 :: "r"(dst), "l"(src), "r"(sz));
}
__device__ __forceinline__ void cp_commit() {
    asm volatile("cp.async.commit_group;" ::: "memory");
}
__device__ __forceinline__ void cp_wait1() {
    asm volatile("cp.async.wait_group 1;" ::: "memory");
}

// ---------------- fused conversion: inp, (q+qpos), Wv, Wout -> fp16 ----------------
#define N8U (LQ * DMOD / 8)     // 1,280,000 units of 8 floats
#define W8U (DMOD * DMOD / 8)   // 8,192
__global__ void conv_fused(const float4* __restrict__ query, const float4* __restrict__ qpos,
                           const float4* __restrict__ inp, const float4* __restrict__ wv,
                           const float4* __restrict__ wout) {
    int i = blockIdx.x * blockDim.x + threadIdx.x;
    if (i < N8U) {
        float4 a = inp[i * 2], b = inp[i * 2 + 1];
        reinterpret_cast<uint4*>(g_inp)[i] = pack8(a, b);
    } else if (i < 2 * N8U) {
        int o = i - N8U;
        float4 a = query[o * 2], b = query[o * 2 + 1];
        float4 c = qpos[o * 2],  d = qpos[o * 2 + 1];
        a.x += c.x; a.y += c.y; a.z += c.z; a.w += c.w;
        b.x += d.x; b.y += d.y; b.z += d.z; b.w += d.w;
        reinterpret_cast<uint4*>(g_q16)[o] = pack8(a, b);
    } else if (i < 2 * N8U + W8U) {
        int o = i - 2 * N8U;
        reinterpret_cast<uint4*>(g_wv)[o] = pack8(wv[o * 2], wv[o * 2 + 1]);
    } else if (i < 2 * N8U + 2 * W8U) {
        int o = i - 2 * N8U - W8U;
        reinterpret_cast<uint4*>(g_wout)[o] = pack8(wout[o * 2], wout[o * 2 + 1]);
    }
}

// ---------------- pad [W_off; W_attn; 0] -> g_woa (fp16) + g_boa ----------------
__global__ void pad_woa(const float4* __restrict__ woff, const float4* __restrict__ wattn,
                        const float* __restrict__ boff, const float* __restrict__ battn) {
    if (blockIdx.x < 16) {
        int i = blockIdx.x * 256 + threadIdx.x;   // unit of 8 floats; 32 units/row
        int row = i >> 5, c8 = i & 31;
        float4 a, b;
        if (row < 64)      { a = woff[row * 64 + c8 * 2];          b = woff[row * 64 + c8 * 2 + 1]; }
        else if (row < 96) { a = wattn[(row - 64) * 64 + c8 * 2];  b = wattn[(row - 64) * 64 + c8 * 2 + 1]; }
        else               { a = make_float4(0, 0, 0, 0); b = a; }
        reinterpret_cast<uint4*>(g_woa)[i] = pack8(a, b);
    } else {
        int t = threadIdx.x;
        if (t < 128)
            g_boa[t] = t < 64 ? boff[t] : (t < 96 ? battn[t - 64] : 0.0f);
    }
}

// ============ shared fp16 GEMM body ============
__device__ __forceinline__ void gemm_body(const __half* __restrict__ A,
                                          const __half* __restrict__ B,
                                          const float* __restrict__ bias,
                                          __half* __restrict__ Ch, float* __restrict__ Cf,
                                          int bn, int N, int M) {
    constexpr int BM = 128, BK = 32, LD = 40;
    constexpr int NCHUNK = DMOD / BK;      // 8
    constexpr int ASZ = BM * LD;
    constexpr int SSZ = 2 * ASZ;

    extern __shared__ __half smh[];
    const uint32_t smem_u32 = (uint32_t)__cvta_generic_to_shared(smh);

    const int tid = threadIdx.x;
    const int wid = tid >> 5;
    const int lane = tid & 31;
    const int wm = wid & 3;
    const int wn = wid >> 2;
    const int bm = blockIdx.y * BM;
    const int lq = lane >> 2;
    const int lr = lane & 3;

    const int arow_l = wm * 32 + (lane & 15);
    const int acol_l = (lane >> 4) << 3;
    const int brow_l = wn * 64 + (lane & 7) + ((lane >> 4) << 3);
    const int bcol_l = ((lane >> 3) & 1) << 3;

    const int r0 = tid >> 2;
    const int f8 = (tid & 3) * 8;
    const __half* abase = A + (size_t)(bm + r0) * DMOD + f8;
    const __half* bbase = B + (size_t)(bn + r0) * DMOD + f8;
    uint32_t asz[2];
#pragma unroll
    for (int i = 0; i < 2; i++) asz[i] = (bm + r0 + 64 * i) < M ? 16u : 0u;

    auto issue_stage = [&](int buf, int k0) {
        const uint32_t sb = smem_u32 + (uint32_t)(buf * SSZ) * 2u;
#pragma unroll
        for (int i = 0; i < 2; i++)
            cp_async16(sb + (uint32_t)((r0 + 64 * i) * LD + f8) * 2u,
                       abase + k0 + (size_t)(64 * i) * DMOD, asz[i]);
#pragma unroll
        for (int i = 0; i < 2; i++)
            cp_async16(sb + (uint32_t)(ASZ + (r0 + 64 * i) * LD + f8) * 2u,
                       bbase + k0 + (size_t)(64 * i) * DMOD, 16u);
    };

    float acc[2][8][4];
#pragma unroll
    for (int i = 0; i < 2; i++)
#pragma unroll
        for (int j = 0; j < 8; j++)
#pragma unroll
            for (int r = 0; r < 4; r++) acc[i][j][r] = 0.0f;

    issue_stage(0, 0); cp_commit();
    issue_stage(1, BK); cp_commit();

    for (int c = 0; c < NCHUNK; c++) {
        cp_wait1();
        __syncthreads();
        if (c + 2 < NCHUNK) issue_stage((c + 2) % 3, (c + 2) * BK);
        cp_commit();

        const uint32_t As_u = smem_u32 + (uint32_t)((c % 3) * SSZ) * 2u;
        const uint32_t Bs_u = As_u + (uint32_t)ASZ * 2u;
#pragma unroll
        for (int ks = 0; ks < 2; ks++) {
            const int kk = ks * 16;
            uint32_t a[2][4], b[4][4];
#pragma unroll
            for (int mi = 0; mi < 2; mi++)
                ldsm4(a[mi][0], a[mi][1], a[mi][2], a[mi][3],
                      As_u + (uint32_t)((arow_l + mi * 16) * LD + kk + acol_l) * 2u);
#pragma unroll
            for (int nb = 0; nb < 4; nb++)
                ldsm4(b[nb][0], b[nb][1], b[nb][2], b[nb][3],
                      Bs_u + (uint32_t)((brow_l + nb * 16) * LD + kk + bcol_l) * 2u);
#pragma unroll
            for (int mi = 0; mi < 2; mi++)
#pragma unroll
                for (int nb = 0; nb < 4; nb++) {
                    mma16n8k16h(acc[mi][nb * 2 + 0], a[mi], &b[nb][0]);
                    mma16n8k16h(acc[mi][nb * 2 + 1], a[mi], &b[nb][2]);
                }
        }
    }

#pragma unroll
    for (int mi = 0; mi < 2; mi++) {
        const int row0 = bm + wm * 32 + mi * 16 + lq;
#pragma unroll
        for (int ni = 0; ni < 8; ni++) {
            const int col = bn + wn * 64 + ni * 8 + lr * 2;
            const float bz0 = bias[col], bz1 = bias[col + 1];
            if (Cf) {
                if (row0 < M)
                    *reinterpret_cast<float2*>(Cf + (size_t)row0 * N + col) =
                        make_float2(acc[mi][ni][0] + bz0, acc[mi][ni][1] + bz1);
                if (row0 + 8 < M)
                    *reinterpret_cast<float2*>(Cf + (size_t)(row0 + 8) * N + col) =
                        make_float2(acc[mi][ni][2] + bz0, acc[mi][ni][3] + bz1);
            } else {
                if (row0 < M)
                    *reinterpret_cast<__half2*>(Ch + (size_t)row0 * N + col) =
                        __floats2half2_rn(acc[mi][ni][0] + bz0, acc[mi][ni][1] + bz1);
                if (row0 + 8 < M)
                    *reinterpret_cast<__half2*>(Ch + (size_t)(row0 + 8) * N + col) =
                        __floats2half2_rn(acc[mi][ni][2] + bz0, acc[mi][ni][3] + bz1);
            }
        }
    }
}

// ---- fused value + oa GEMM ----
__global__ __launch_bounds__(256, 2)
void valoa_gemm(const float* __restrict__ bv) {
    if (blockIdx.x < 2)
        gemm_body(g_inp, g_wv, bv, g_value, nullptr, blockIdx.x * 128, DMOD, LQ);
    else
        gemm_body(g_q16, g_woa, g_boa, nullptr, g_oa, 0, 128, LQ);
}

// ---- output GEMM ----
__global__ __launch_bounds__(256, 2)
void out_gemm(const float* __restrict__ bout, float* __restrict__ out) {
    gemm_body(g_sampled, g_wout, bout, nullptr, out, blockIdx.x * 128, DMOD, LQ);
}

// ---------------- sampler: scalar phase + dual-head half2 gather ----------------
__global__ __launch_bounds__(256)
void sample_kernel(const float* __restrict__ refpts) {
    __shared__ int2 s_pc[256 * 4];   // (row idx, fp32 weight) per (q,h,p,corner)

    const int tid = threadIdx.x;
    const int q0 = blockIdx.x * GQ;
    const int qi = tid >> 5;
    const int h = (tid >> 2) & 7;
    const int p = tid & 3;
    const int q = q0 + qi;

    // ---- scalar phase: one thread per (q,h,p) ----
    const float refx = refpts[q * 2 + 0];
    const float refy = refpts[q * 2 + 1];
    const float* row = g_oa + (size_t)q * 128;
    const float lg = row[64 + h * 4 + p];
    const float ox = row[h * 8 + p * 2 + 0];
    const float oy = row[h * 8 + p * 2 + 1];

    float mx = lg;
    mx = fmaxf(mx, __shfl_xor_sync(0xFFFFFFFFu, mx, 1));
    mx = fmaxf(mx, __shfl_xor_sync(0xFFFFFFFFu, mx, 2));
    float e = expf(lg - mx);
    float s = e;
    s += __shfl_xor_sync(0xFFFFFFFFu, s, 1);
    s += __shfl_xor_sync(0xFFFFFFFFu, s, 2);
    const float ap = e / s;

    const float x = (refx + ox * (1.0f / WSP)) * WSP - 0.5f;
    const float y = (refy + oy * (1.0f / HSP)) * HSP - 0.5f;
    const float x0f = floorf(x), y0f = floorf(y);
    const int x0 = (int)x0f, y0 = (int)y0f;
    const float lw = x - x0f, lh = y - y0f;
    const int x1 = x0 + 1, y1 = y0 + 1;

    const float wc[4] = { (1.0f - lh) * (1.0f - lw), (1.0f - lh) * lw,
                          lh * (1.0f - lw),          lh * lw };
    const int xs[4] = { x0, x1, x0, x1 };
    const int ys[4] = { y0, y0, y1, y1 };
#pragma unroll
    for (int c = 0; c < 4; c++) {
        const bool v = (xs[c] >= 0) & (xs[c] < WSP) & (ys[c] >= 0) & (ys[c] < HSP);
        const float w = v ? ap * wc[c] : 0.0f;
        const int idx = v ? (ys[c] * WSP + xs[c]) : 0;
        s_pc[tid * 4 + c] = make_int2(idx, __float_as_int(w));
    }
    __syncthreads();

    // ---- gather phase: warp = query; lanes 0-15 head 2hh, lanes 16-31 head 2hh+1;
    //      each lane covers a channel PAIR via __half2 ----
    const int wid = tid >> 5, lane = tid & 31;
    const int half = lane >> 4;            // which head of the pair
    const int ci = lane & 15;              // channel-pair index (2*ci, 2*ci+1)
    const int gq = q0 + wid;

#pragma unroll
    for (int hh = 0; hh < 4; hh++) {
        const int head = hh * 2 + half;
        const __half2* vb = reinterpret_cast<const __half2*>(
            g_value + head * DH + ci * 2);
        const int sbase = (wid * 32 + head * 4) * 4;   // 16 corners for this head
        float ax = 0.0f, ay = 0.0f;
#pragma unroll
        for (int pc = 0; pc < 16; pc++) {
            int2 ew = s_pc[sbase + pc];
            const float w = __int_as_float(ew.y);
            float2 vf = __half22float2(vb[(size_t)ew.x * (DMOD / 2)]);
            ax += w * vf.x;
            ay += w * vf.y;
        }
        *reinterpret_cast<__half2*>(
            g_sampled + (size_t)gq * DMOD + head * DH + ci * 2) =
            __floats2half2_rn(ax, ay);
    }
}

// ---------------- launch ----------------
extern "C" void kernel_launch(void* const* d_in, const int* in_sizes, int n_in,
                              void* d_out, int out_size) {
    const float* query  = (const float*)d_in[0];
    const float* qpos   = (const float*)d_in[1];
    const float* refpts = (const float*)d_in[2];
    const float* inp    = (const float*)d_in[3];
    const float* Wv     = (const float*)d_in[4];
    const float* bv     = (const float*)d_in[5];
    const float* Woff   = (const float*)d_in[6];
    const float* boff   = (const float*)d_in[7];
    const float* Wattn  = (const float*)d_in[8];
    const float* battn  = (const float*)d_in[9];
    const float* Wout   = (const float*)d_in[10];
    const float* bout   = (const float*)d_in[11];
    float* out = (float*)d_out;

    const int gy = (LQ + 127) / 128;  // 313
    const int SMEM_PIPE = 3 * (2 * 128 * 40) * 2;  // 61440
    cudaFuncSetAttribute(valoa_gemm, cudaFuncAttributeMaxDynamicSharedMemorySize, SMEM_PIPE);
    cudaFuncSetAttribute(out_gemm,   cudaFuncAttributeMaxDynamicSharedMemorySize, SMEM_PIPE);

    // 0. conversions
    {
        int total = 2 * N8U + 2 * W8U;
        conv_fused<<<(total + 255) / 256, 256>>>(
            (const float4*)query, (const float4*)qpos, (const float4*)inp,
            (const float4*)Wv, (const float4*)Wout);
        pad_woa<<<17, 256>>>((const float4*)Woff, (const float4*)Wattn, boff, battn);
    }

    // 1. fused: value projection (x<2) + [off|attn] projection (x==2)
    valoa_gemm<<<dim3(3, gy), 256, SMEM_PIPE>>>(bv);

    // 2. fused softmax + bilinear sampling
    sample_kernel<<<LQ / GQ, 256>>>(refpts);

    // 3. out = sampled @ W_out^T + b_out
    out_gemm<<<dim3(2, gy), 256, SMEM_PIPE>>>(bout, out);
}